// round 8
// baseline (speedup 1.0000x reference)
#include <cuda_runtime.h>
#include <cstdint>

#define BB 16
#define NN 3000
#define MM 300
#define KK 4
#define LL 80
#define PCAP 128
#define GCAP 32
#define TPB 128
#define THRESH 0.6f

__device__ __forceinline__ float neg_inf() { return __int_as_float(0xff800000); }

// ---------------- global bucket scratch (zero-init at load; kMain restores) -
__device__ int    g_pcnt[BB * LL];
__device__ int    g_gcnt[BB * LL];
__device__ float4 g_p1[BB * LL * PCAP];   // proposal (x0,y0,x1,y1)
__device__ float2 g_p2[BB * LL * PCAP];   // proposal (area, n_as_bits)
__device__ float4 g_g1[BB * LL * GCAP];   // gt (x0,y0,x1,y1)
__device__ float2 g_g2[BB * LL * GCAP];   // gt (area, m_as_bits)

// ---------------- exact-order IoU helpers (no FMA contraction) -------------
struct BoxA { float x0, y0, x1, y1, area; };

__device__ __forceinline__ BoxA cvt_box(float cx, float cy, float w, float h) {
    BoxA r;
    float hw = __fmul_rn(0.5f, w);
    float hh = __fmul_rn(0.5f, h);
    r.x0 = __fsub_rn(cx, hw);
    r.y0 = __fsub_rn(cy, hh);
    r.x1 = __fadd_rn(cx, hw);
    r.y1 = __fadd_rn(cy, hh);
    r.area = __fmul_rn(__fsub_rn(r.x1, r.x0), __fsub_rn(r.y1, r.y0));
    return r;
}

// a = gt box, b = proposal box (union = area_a + area_b - inter, in that order)
__device__ __forceinline__ float iou_ab(const BoxA& a, const BoxA& b) {
    float ltx = fmaxf(a.x0, b.x0);
    float lty = fmaxf(a.y0, b.y0);
    float rbx = fminf(a.x1, b.x1);
    float rby = fminf(a.y1, b.y1);
    float wx = fmaxf(__fsub_rn(rbx, ltx), 0.0f);
    float wy = fmaxf(__fsub_rn(rby, lty), 0.0f);
    float inter = __fmul_rn(wx, wy);
    float uni = __fsub_rn(__fadd_rn(a.area, b.area), inter);
    return __fdiv_rn(inter, fmaxf(uni, 1e-9f));
}

// total order: (value desc, index asc) — order-independent, tie-safe
__device__ __forceinline__ bool cmpvi(float v, int i, float w, int j) {
    return (v > w) || (v == w && i < j);
}

__device__ __forceinline__ float sel4f(float v0, float v1, float v2, float v3, int i) {
    float r = v3;
    r = (i == 2) ? v2 : r;
    r = (i == 1) ? v1 : r;
    r = (i == 0) ? v0 : r;
    return r;
}
__device__ __forceinline__ int sel4i(int v0, int v1, int v2, int v3, int i) {
    int r = v3;
    r = (i == 2) ? v2 : r;
    r = (i == 1) ? v1 : r;
    r = (i == 0) ? v0 : r;
    return r;
}

// ---------------- kernel S: single scan -> converted bucket records ---------
__global__ void __launch_bounds__(256) kS(const float* __restrict__ props,
                                          const int* __restrict__ pinds,
                                          const float* __restrict__ gtb,
                                          const int* __restrict__ gtl) {
    int i = blockIdx.x * 256 + threadIdx.x;
    if (i < BB * NN) {
        int b = i / NN, n = i % NN;
        int lab = pinds[i];
        if ((unsigned)lab < LL) {
            int bk = b * LL + lab;
            int slot = atomicAdd(&g_pcnt[bk], 1);
            if (slot < PCAP) {
                float4 p4 = reinterpret_cast<const float4*>(props)[i];
                BoxA p = cvt_box(p4.x, p4.y, p4.z, p4.w);
                size_t idx = (size_t)bk * PCAP + slot;
                g_p1[idx] = make_float4(p.x0, p.y0, p.x1, p.y1);
                g_p2[idx] = make_float2(p.area, __int_as_float(n));
            }
        }
    } else if (i < BB * NN + BB * MM) {
        int j = i - BB * NN;
        int b = j / MM, m = j % MM;
        int lab = gtl[j];
        if ((unsigned)lab < LL) {
            int bk = b * LL + lab;
            int slot = atomicAdd(&g_gcnt[bk], 1);
            if (slot < GCAP) {
                float4 g4 = reinterpret_cast<const float4*>(gtb)[j];
                BoxA g = cvt_box(g4.x, g4.y, g4.z, g4.w);
                size_t idx = (size_t)bk * GCAP + slot;
                g_g1[idx] = make_float4(g.x0, g.y0, g.x1, g.y1);
                g_g2[idx] = make_float2(g.area, __int_as_float(m));
            }
        }
    }
}

// ---------------- kernel M: one block per (batch,label) bucket --------------
__global__ void __launch_bounds__(TPB)
kMain(float* __restrict__ out) {
    __shared__ float spx0[PCAP], spy0[PCAP], spx1[PCAP], spy1[PCAP], spar[PCAP];
    __shared__ int   spn[PCAP];
    __shared__ float sgx0[GCAP], sgy0[GCAP], sgx1[GCAP], sgy1[GCAP], sgar[GCAP], sgmx[GCAP];
    __shared__ int   sgm[GCAP];
    __shared__ int   scnt[GCAP];
    __shared__ float stv[GCAP * KK];
    __shared__ int   sti[GCAP * KK];
    __shared__ int   s_pc, s_gc;

    const int bk = blockIdx.x;          // = b * LL + lab
    const int b  = bk / LL;
    const int t  = threadIdx.x;

    if (t == 0) {
        s_pc = g_pcnt[bk];
        s_gc = g_gcnt[bk];
        g_pcnt[bk] = 0;                 // restore zero-invariant for next replay
        g_gcnt[bk] = 0;
    }
    if (t < GCAP) scnt[t] = 0;
    __syncthreads();

    const int gc = min(s_gc, GCAP);
    if (gc == 0) return;                // no GT rows owned by this block
    const int pc = min(s_pc, PCAP);

    // ---- load bucket records into smem (coalesced) ----
    for (int i = t; i < pc; i += TPB) {
        float4 q1 = g_p1[(size_t)bk * PCAP + i];
        float2 q2 = g_p2[(size_t)bk * PCAP + i];
        spx0[i] = q1.x; spy0[i] = q1.y; spx1[i] = q1.z; spy1[i] = q1.w;
        spar[i] = q2.x; spn[i] = __float_as_int(q2.y);
    }
    if (t < gc) {
        float4 q1 = g_g1[(size_t)bk * GCAP + t];
        float2 q2 = g_g2[(size_t)bk * GCAP + t];
        sgx0[t] = q1.x; sgy0[t] = q1.y; sgx1[t] = q1.z; sgy1[t] = q1.w;
        sgar[t] = q2.x; sgm[t] = __float_as_int(q2.y);
    }
    __syncthreads();

    // ---- phase A: warp per GT slot -> gmax + stable top-4 ----
    {
        const int warp = t >> 5, lane = t & 31;
        for (int j = warp; j < gc; j += TPB / 32) {
            BoxA g;
            g.x0 = sgx0[j]; g.y0 = sgy0[j]; g.x1 = sgx1[j]; g.y1 = sgy1[j]; g.area = sgar[j];

            float tv0 = neg_inf(), tv1 = neg_inf(), tv2 = neg_inf(), tv3 = neg_inf();
            int   ti0 = 0x7fffffff, ti1 = 0x7fffffff, ti2 = 0x7fffffff, ti3 = 0x7fffffff;

            for (int i = lane; i < pc; i += 32) {
                BoxA p;
                p.x0 = spx0[i]; p.y0 = spy0[i]; p.x1 = spx1[i]; p.y1 = spy1[i]; p.area = spar[i];
                int n = spn[i];
                float v = iou_ab(g, p);
                if (cmpvi(v, n, tv3, ti3)) {
                    if (cmpvi(v, n, tv0, ti0)) {
                        tv3 = tv2; ti3 = ti2; tv2 = tv1; ti2 = ti1; tv1 = tv0; ti1 = ti0;
                        tv0 = v; ti0 = n;
                    } else if (cmpvi(v, n, tv1, ti1)) {
                        tv3 = tv2; ti3 = ti2; tv2 = tv1; ti2 = ti1;
                        tv1 = v; ti1 = n;
                    } else if (cmpvi(v, n, tv2, ti2)) {
                        tv3 = tv2; ti3 = ti2;
                        tv2 = v; ti2 = n;
                    } else {
                        tv3 = v; ti3 = n;
                    }
                }
            }

            // warp butterfly merge of sorted-4 lists (total order -> all lanes agree)
#pragma unroll
            for (int off = 16; off > 0; off >>= 1) {
                float bv0 = __shfl_xor_sync(0xffffffffu, tv0, off);
                float bv1 = __shfl_xor_sync(0xffffffffu, tv1, off);
                float bv2 = __shfl_xor_sync(0xffffffffu, tv2, off);
                float bv3 = __shfl_xor_sync(0xffffffffu, tv3, off);
                int   bi0 = __shfl_xor_sync(0xffffffffu, ti0, off);
                int   bi1 = __shfl_xor_sync(0xffffffffu, ti1, off);
                int   bi2 = __shfl_xor_sync(0xffffffffu, ti2, off);
                int   bi3 = __shfl_xor_sync(0xffffffffu, ti3, off);
                float cv[4]; int ci[4];
                int ia = 0, ib = 0;
#pragma unroll
                for (int q = 0; q < 4; q++) {
                    float A  = sel4f(tv0, tv1, tv2, tv3, ia);
                    int   Ai = sel4i(ti0, ti1, ti2, ti3, ia);
                    float Bv = sel4f(bv0, bv1, bv2, bv3, ib);
                    int   Bi = sel4i(bi0, bi1, bi2, bi3, ib);
                    bool ta = cmpvi(A, Ai, Bv, Bi);
                    cv[q] = ta ? A : Bv;
                    ci[q] = ta ? Ai : Bi;
                    ia += ta ? 1 : 0;
                    ib += ta ? 0 : 1;
                }
                tv0 = cv[0]; tv1 = cv[1]; tv2 = cv[2]; tv3 = cv[3];
                ti0 = ci[0]; ti1 = ci[1]; ti2 = ci[2]; ti3 = ci[3];
            }

            if (lane == 0) {
                sgmx[j] = tv0;
                stv[j * KK + 0] = tv0; stv[j * KK + 1] = tv1;
                stv[j * KK + 2] = tv2; stv[j * KK + 3] = tv3;
                sti[j * KK + 0] = ti0; sti[j * KK + 1] = ti1;
                sti[j * KK + 2] = ti2; sti[j * KK + 3] = ti3;
            }
        }
    }
    __syncthreads();

    // ---- phase B: thread per proposal -> argmax over bucket GTs -> counts ----
    for (int i = t; i < pc; i += TPB) {
        BoxA p;
        p.x0 = spx0[i]; p.y0 = spy0[i]; p.x1 = spx1[i]; p.y1 = spy1[i]; p.area = spar[i];

        float bestv = neg_inf();
        int bestm = 0x7fffffff, bestj = 0;
        bool lq = false;
        for (int j = 0; j < gc; j++) {
            BoxA g;
            g.x0 = sgx0[j]; g.y0 = sgy0[j]; g.x1 = sgx1[j]; g.y1 = sgy1[j]; g.area = sgar[j];
            float v = iou_ab(g, p);                 // identical bits to phase A
            if (v == sgmx[j]) lq = true;
            int m = sgm[j];
            if (v > bestv || (v == bestv && m < bestm)) { bestv = v; bestm = m; bestj = j; }
        }
        // matching IoU >= 0 beats all non-matching NEG entries -> bestm == ref best_gt
        if (bestv >= THRESH || lq)
            atomicAdd(&scnt[bestj], 1);
    }
    __syncthreads();

    // ---- phase C: write output rows owned by this block ----
    for (int j = t; j < gc; j += TPB) {
        const int m = sgm[j];
        const int bm = b * MM + m;
        int take = scnt[j];
        take = take < KK ? take : KK;
        const int S = BB * MM * KK;
#pragma unroll
        for (int q = 0; q < KK; q++) {
            bool val = q < take;
            out[bm * KK + q]         = val ? (float)sti[j * KK + q] : -1.0f;
            out[S + bm * KK + q]     = val ? (float)m : -1.0f;
            out[2 * S + bm * KK + q] = val ? 1.0f : 0.0f;
            out[3 * S + bm * KK + q] = val ? stv[j * KK + q] : 0.0f;
        }
    }
}

// ---------------- launch ----------------------------------------------------
extern "C" void kernel_launch(void* const* d_in, const int* in_sizes, int n_in,
                              void* d_out, int out_size) {
    // metadata order: pred_logits_match, pred_boxes, init_reference,
    //                 prompt_inds, gt_labels, gt_boxes, max_k
    const float* props = (const float*)d_in[2];   // init_reference (B,N,4)
    const int*   pinds = (const int*)d_in[3];     // prompt_inds    (B,N)
    const int*   gtl   = (const int*)d_in[4];     // gt_labels      (B,M)
    const float* gtb   = (const float*)d_in[5];   // gt_boxes       (B,M,4)

    kS<<<(BB * NN + BB * MM + 255) / 256, 256>>>(props, pinds, gtb, gtl);
    kMain<<<BB * LL, TPB>>>((float*)d_out);
}